// round 8
// baseline (speedup 1.0000x reference)
#include <cuda_runtime.h>
#include <cuda_fp16.h>
#include <cstdint>

#define BATCH 8
#define SEQ   2048
#define EMB   1024
#define HD    128

#define N_PROJ 256            // 128 token-tiles x {K,V}
#define N_ATTN 576            // 72 items x 8 batches
#define N_ITEMS (N_PROJ + N_ATTN)

// ---------------- scratch (allocation-free rule) ----------------
__device__ __half g_Kh [BATCH * SEQ * HD];       // K = x@Wk, fp16, h interleaved-16
__device__ __half g_Vth[BATCH * HD * SEQ];       // V^T [b][h][t], fp16, t interleaved-16
__device__ __half g_Wh [2 * HD * EMB];           // [Wk^T;Wv^T] [n=256][c=1024], c interleaved-16
__device__ float  g_Opart[8 * BATCH * SEQ * HD]; // per-chunk unnormalized O
__device__ float  g_lpart[8 * BATCH * SEQ];      // per-chunk row sums
__device__ int    g_cnt[BATCH * 16];             // per (b, qt) finished-chunk counters
__device__ int    g_qhead;                       // work queue head
__device__ int    g_pflagK[128];                 // per 128-token tile: K ready
__device__ int    g_pflagV[128];                 // per 128-token tile: V ready

// Attn items (per batch): (qt, ch). chunk ch covers kv128 tiles [2ch, min(2ch+2, qt+1)).
__constant__ unsigned char ITEM_QT[72] = {
    15,15,15,15,15,15,15,15, 14,14,14,14,14,14,14, 13,13,13,13,13,13,13,
    12,12,12,12,12,12, 11,11,11,11,11,11, 10,10,10,10,10, 9,9,9,9,9,
    8,8,8,8, 7,7,7,7, 6,6,6, 5,5,5, 4,4, 3,3, 2, 1,
    14,12,10,8,6,4,2,0 };
__constant__ unsigned char ITEM_CH[72] = {
    0,1,2,3,4,5,6,7, 0,1,2,3,4,5,6, 0,1,2,3,4,5,6,
    0,1,2,3,4,5, 0,1,2,3,4,5, 0,1,2,3,4, 0,1,2,3,4,
    0,1,2,3, 0,1,2,3, 0,1,2, 0,1,2, 0,1, 0,1, 0, 0,
    7,6,5,4,3,2,1,0 };

// ---------------- helpers ----------------
__device__ __forceinline__ void cp16(void* s, const void* g) {
    asm volatile("cp.async.cg.shared.global [%0], [%1], 16;"
                 :: "r"((uint32_t)__cvta_generic_to_shared(s)), "l"(g));
}
#define CP_COMMIT() asm volatile("cp.async.commit_group;" ::: "memory")
template <int N>
__device__ __forceinline__ void cp_wait() {
    asm volatile("cp.async.wait_group %0;" :: "n"(N) : "memory");
}
__device__ __forceinline__ uint32_t packh2(float lo, float hi) {
    uint32_t d;
    asm("cvt.rn.f16x2.f32 %0, %1, %2;" : "=r"(d) : "f"(hi), "f"(lo));
    return d;
}
__device__ __forceinline__ void mma16(float* d, const uint32_t* a, uint32_t b0, uint32_t b1) {
    asm volatile("mma.sync.aligned.m16n8k16.row.col.f32.f16.f16.f32 "
        "{%0,%1,%2,%3}, {%4,%5,%6,%7}, {%8,%9}, {%0,%1,%2,%3};"
        : "+f"(d[0]), "+f"(d[1]), "+f"(d[2]), "+f"(d[3])
        : "r"(a[0]), "r"(a[1]), "r"(a[2]), "r"(a[3]), "r"(b0), "r"(b1));
}
__device__ __forceinline__ int pos16(int c) {   // [0,1,8,9,2,3,10,11,4,5,12,13,6,7,14,15]
    return 4 * ((c & 7) >> 1) + 2 * ((c >> 3) & 1) + (c & 1);
}
__device__ __forceinline__ void waitflag(const int* p) {
    int v;
    asm volatile("ld.acquire.gpu.global.b32 %0, [%1];" : "=r"(v) : "l"(p));
    while (!v) {
        __nanosleep(64);
        asm volatile("ld.acquire.gpu.global.b32 %0, [%1];" : "=r"(v) : "l"(p));
    }
}
__device__ __forceinline__ void setflag(int* p) {
    asm volatile("st.release.gpu.global.b32 [%0], %1;" :: "l"(p), "r"(1));
}

// ---------------------------------------------------------------------------
// Kernel 0: W -> g_Wh (half, transposed, c interleaved-16); reset queue/flags.
// ---------------------------------------------------------------------------
__global__ void transpose_w(const float* __restrict__ Wk, const float* __restrict__ Wv) {
    __shared__ float t[32][33];
    if (blockIdx.x == 0 && blockIdx.y == 0) {
        int f = threadIdx.y * 32 + threadIdx.x;
        if (f < 128) { g_cnt[f] = 0; g_pflagK[f] = 0; g_pflagV[f] = 0; }
        if (f == 128) g_qhead = 0;
    }
    const int n0 = blockIdx.x * 32;
    const int c0 = blockIdx.y * 32;
    const float* W = (blockIdx.x < 4) ? Wk : Wv;
    const int nb = (blockIdx.x & 3) * 32;
    for (int r = threadIdx.y; r < 32; r += 8)
        t[r][threadIdx.x] = W[(size_t)(c0 + r) * HD + nb + threadIdx.x];
    __syncthreads();
    for (int r = threadIdx.y; r < 32; r += 8) {
        int c = c0 + threadIdx.x;
        int cs = (c & ~15) + pos16(c & 15);
        g_Wh[(size_t)(n0 + r) * EMB + cs] = __float2half(t[threadIdx.x][r]);
    }
}

// ---------------- fused kernel layout constants ----------------
// proj stage: A f32 [128][72 pad] (288B rows) + B half [128][80 pad] (160B rows)
#define PJ_AB 36864
#define PJ_ST (36864 + 20480)      // 57344 B per stage, x2 = 114688
// attn: K [128][144h] x2, V [128][144h] x2 (halves)
#define KT0 0
#define KT1 18432
#define VT0 36864
#define VT1 55296
#define FU_SMEM 147456             // bytes (attn dominates)

// ---------------------------------------------------------------------------
// proj item: C[128m x 128n] = x_tile @ W(wsel).  8 warps = 4m x 2n.
// ---------------------------------------------------------------------------
__device__ __forceinline__ void do_proj(int item, const float* __restrict__ x, char* smc) {
    const int tid = threadIdx.x, w = tid >> 5, lane = tid & 31;
    const int gid = lane >> 2, tig = lane & 3;
    const int wm = w & 3, wn = w >> 2;
    const int mt = item >> 1, wsel = item & 1;
    const int m0 = mt * 128;

    float acc[16][4];
#pragma unroll
    for (int t = 0; t < 16; t++)
#pragma unroll
        for (int v = 0; v < 4; v++) acc[t][v] = 0.0f;

    auto issue = [&](int st, int c) {
        char* As = smc + st * PJ_ST;
        char* Bs = As + PJ_AB;
#pragma unroll
        for (int q = 0; q < 8; q++) {     // A: 128 rows x 256B
            int f = q * 256 + tid, r = f >> 4, seg = f & 15;
            cp16(As + r * 288 + seg * 16, &x[(size_t)(m0 + r) * EMB + c * 64 + seg * 4]);
        }
#pragma unroll
        for (int q = 0; q < 4; q++) {     // B: 128 rows x 128B (halves)
            int f = q * 256 + tid, r = f >> 3, seg = f & 7;
            cp16(Bs + r * 160 + seg * 16, &g_Wh[(size_t)(wsel * 128 + r) * EMB + c * 64 + seg * 8]);
        }
    };

    issue(0, 0); CP_COMMIT();

    for (int c = 0; c < 16; c++) {
        if (c + 1 < 16) issue((c + 1) & 1, c + 1);
        CP_COMMIT();
        cp_wait<1>();
        __syncthreads();

        const float* As = (const float*)(smc + (c & 1) * PJ_ST);
        const __half* Bs = (const __half*)(smc + (c & 1) * PJ_ST + PJ_AB);
#pragma unroll
        for (int ks = 0; ks < 4; ks++) {
            uint32_t a[2][4];
#pragma unroll
            for (int mi = 0; mi < 2; mi++) {
                int r = 32 * wm + 16 * mi + gid;
                float2 lo0 = *(const float2*)(As + r * 72 + 16 * ks + 2 * tig);
                float2 lo1 = *(const float2*)(As + (r + 8) * 72 + 16 * ks + 2 * tig);
                float2 hi0 = *(const float2*)(As + r * 72 + 16 * ks + 2 * tig + 8);
                float2 hi1 = *(const float2*)(As + (r + 8) * 72 + 16 * ks + 2 * tig + 8);
                a[mi][0] = packh2(lo0.x, lo0.y);
                a[mi][1] = packh2(lo1.x, lo1.y);
                a[mi][2] = packh2(hi0.x, hi0.y);
                a[mi][3] = packh2(hi1.x, hi1.y);
            }
#pragma unroll
            for (int ni = 0; ni < 8; ni++) {
                uint2 bb = *(const uint2*)(Bs + (64 * wn + 8 * ni + gid) * 80 + 16 * ks + 4 * tig);
                mma16(acc[ni],     a[0], bb.x, bb.y);
                mma16(acc[8 + ni], a[1], bb.x, bb.y);
            }
        }
        __syncthreads();
    }

    if (wsel == 0) {
        // g_Kh, h interleaved-16
#pragma unroll
        for (int mi = 0; mi < 2; mi++) {
            int r0 = m0 + 32 * wm + 16 * mi + gid;
#pragma unroll
            for (int ni = 0; ni < 8; ni++) {
                int n = 64 * wn + 8 * ni + 2 * tig;
                int hst = (n & ~15) + pos16(n & 15);
                *(__half2*)&g_Kh[(size_t)r0 * HD + hst] =
                    __floats2half2_rn(acc[mi * 8 + ni][0], acc[mi * 8 + ni][1]);
                *(__half2*)&g_Kh[(size_t)(r0 + 8) * HD + hst] =
                    __floats2half2_rn(acc[mi * 8 + ni][2], acc[mi * 8 + ni][3]);
            }
        }
    } else {
        // V^T: stage [h=128][t=128 pad 136] in smem, then coalesced 16B stores.
        __half* vs = (__half*)smc;
#pragma unroll
        for (int mi = 0; mi < 2; mi++) {
            int tl = 32 * wm + 16 * mi + gid;
            int ts0 = (tl & ~15) + pos16(tl & 15);
            int ts1 = ts0 + 2;                    // pos16(gid+8) = pos16(gid)+2
#pragma unroll
            for (int ni = 0; ni < 8; ni++) {
                int n = 64 * wn + 8 * ni + 2 * tig;
                vs[n * 136 + ts0]       = __float2half(acc[mi * 8 + ni][0]);
                vs[(n + 1) * 136 + ts0] = __float2half(acc[mi * 8 + ni][1]);
                vs[n * 136 + ts1]       = __float2half(acc[mi * 8 + ni][2]);
                vs[(n + 1) * 136 + ts1] = __float2half(acc[mi * 8 + ni][3]);
            }
        }
        __syncthreads();
        const int bb = m0 >> 11;
        const int tb = m0 & 2047;
        __half* dst = g_Vth + (size_t)bb * HD * SEQ;
        int r = tid >> 1, off = (tid & 1) * 64;
#pragma unroll
        for (int k = 0; k < 8; k++) {
            uint4 v = *(uint4*)&vs[r * 136 + off + k * 8];
            *(uint4*)&dst[(size_t)r * SEQ + tb + off + k * 8] = v;
        }
    }
    __threadfence();
    __syncthreads();
    if (tid == 0) setflag(wsel == 0 ? &g_pflagK[mt] : &g_pflagV[mt]);
}

// ---------------------------------------------------------------------------
// attn item (qt, ch): 128 q-rows, kv128 tiles jj in [2ch, min(2ch+2, qt+1)).
// ---------------------------------------------------------------------------
__device__ __forceinline__ void do_attn(int j, float* __restrict__ out, char* smc) {
    __half* smh = (__half*)smc;
    const int tid = threadIdx.x, w = tid >> 5, lane = tid & 31;
    const int gid = lane >> 2, tig = lane & 3;
    const int b = j & 7;
    const int idx = j >> 3;
    const int qt = ITEM_QT[idx];
    const int ch = ITEM_CH[idx];
    const int jbeg = 2 * ch;
    const int jend = min(2 * ch + 2, qt + 1);
    const int nch = (qt + 2) >> 1;
    const float SCALE = 0.08838834764831845f;

    // dependencies: Q tile (K), kv tiles 2ch, 2ch+1 (K and V)
    waitflag(&g_pflagK[b * 16 + qt]);
    waitflag(&g_pflagK[b * 16 + 2 * ch]);
    waitflag(&g_pflagK[b * 16 + 2 * ch + 1]);
    waitflag(&g_pflagV[b * 16 + 2 * ch]);
    waitflag(&g_pflagV[b * 16 + 2 * ch + 1]);

    const __half* Kbh  = g_Kh  + (size_t)b * SEQ * HD;
    const __half* Vtbh = g_Vth + (size_t)b * HD * SEQ;

    const int KOFF[2] = {KT0, KT1};
    const int VOFF[2] = {VT0, VT1};

    auto stage = [&](int jj, int bsel) {
        const int tok0 = jj * 128;
        __half* Ks = smh + KOFF[bsel];
        __half* Vs = smh + VOFF[bsel];
#pragma unroll
        for (int q = 0; q < 8; q++) {
            int f = q * 256 + tid, r = f >> 4, seg = f & 15;
            cp16(Ks + r * 144 + seg * 8, &Kbh[(size_t)(tok0 + r) * HD + seg * 8]);
        }
#pragma unroll
        for (int q = 0; q < 8; q++) {
            int f = q * 256 + tid, r = f >> 4, seg = f & 15;
            cp16(Vs + r * 144 + seg * 8, &Vtbh[(size_t)r * SEQ + tok0 + seg * 8]);
        }
    };

    stage(jbeg, 0); CP_COMMIT();

    // Q fragments from gmem (q = key(x) source bug: read g_Kh)
    const int qrow = qt * 128 + 16 * w + gid;
    const uint2* Qg0 = (const uint2*)(Kbh + (size_t)qrow * HD);
    const uint2* Qg8 = (const uint2*)(Kbh + (size_t)(qrow + 8) * HD);
    uint32_t qa[8][4];
#pragma unroll
    for (int ks = 0; ks < 8; ks++) {
        uint2 u0 = Qg0[4 * ks + tig];
        uint2 u1 = Qg8[4 * ks + tig];
        qa[ks][0] = u0.x; qa[ks][2] = u0.y;
        qa[ks][1] = u1.x; qa[ks][3] = u1.y;
    }

    float o[16][4];
#pragma unroll
    for (int t = 0; t < 16; t++)
#pragma unroll
        for (int v = 0; v < 4; v++) o[t][v] = 0.0f;
    float l0 = 0.0f, l1 = 0.0f;

    const int qr0 = qt * 128 + 16 * w;

    for (int jj = jbeg; jj < jend; jj++) {
        const int buf = (jj - jbeg) & 1;
        if (jj + 1 < jend) stage(jj + 1, buf ^ 1);
        CP_COMMIT();
        cp_wait<1>();
        __syncthreads();

        const int kv0 = jj * 128;
        if (kv0 <= qr0 + 15) {
            const __half* Ks = smh + KOFF[buf];
            const __half* Vs = smh + VOFF[buf];

            float s[16][4];
#pragma unroll
            for (int t = 0; t < 16; t++)
#pragma unroll
                for (int v = 0; v < 4; v++) s[t][v] = 0.0f;

#pragma unroll
            for (int ks = 0; ks < 8; ks++) {
#pragma unroll
                for (int t = 0; t < 16; t++) {
                    uint2 bb = *(const uint2*)(Ks + (8 * t + gid) * 144 + 16 * ks + 4 * tig);
                    mma16(s[t], qa[ks], bb.x, bb.y);
                }
            }

            const bool domask = (kv0 + 127 > qr0);
#pragma unroll
            for (int t = 0; t < 16; t++) {
                const int col = kv0 + 8 * t + 2 * tig;
                float p0 = __expf(s[t][0] * SCALE);
                float p1 = __expf(s[t][1] * SCALE);
                float p2 = __expf(s[t][2] * SCALE);
                float p3 = __expf(s[t][3] * SCALE);
                if (domask) {
                    const int r0 = qr0 + gid, r1 = r0 + 8;
                    if (col > r0)     p0 = 0.0f;
                    if (col + 1 > r0) p1 = 0.0f;
                    if (col > r1)     p2 = 0.0f;
                    if (col + 1 > r1) p3 = 0.0f;
                }
                l0 += p0 + p1;
                l1 += p2 + p3;
                s[t][0] = p0; s[t][1] = p1; s[t][2] = p2; s[t][3] = p3;
            }

#pragma unroll
            for (int ks = 0; ks < 8; ks++) {
                uint32_t a[4];
                a[0] = packh2(s[2 * ks][0],     s[2 * ks][1]);
                a[1] = packh2(s[2 * ks][2],     s[2 * ks][3]);
                a[2] = packh2(s[2 * ks + 1][0], s[2 * ks + 1][1]);
                a[3] = packh2(s[2 * ks + 1][2], s[2 * ks + 1][3]);
#pragma unroll
                for (int t = 0; t < 16; t++) {
                    uint2 bb = *(const uint2*)(Vs + (8 * t + gid) * 144 + 16 * ks + 4 * tig);
                    mma16(o[t], a, bb.x, bb.y);
                }
            }
        }
        __syncthreads();
    }

#pragma unroll
    for (int off = 1; off < 4; off <<= 1) {
        l0 += __shfl_xor_sync(0xffffffffu, l0, off);
        l1 += __shfl_xor_sync(0xffffffffu, l1, off);
    }

    const int row0 = qt * 128 + 16 * w + gid;
    if (nch == 1) {
        const float i0 = 1.0f / l0, i1 = 1.0f / l1;
#pragma unroll
        for (int t = 0; t < 16; t++) {
            int h = 8 * t + 2 * tig;
            *(float2*)&out[((size_t)b * SEQ + row0) * HD + h] =
                make_float2(o[t][0] * i0, o[t][1] * i0);
            *(float2*)&out[((size_t)b * SEQ + row0 + 8) * HD + h] =
                make_float2(o[t][2] * i1, o[t][3] * i1);
        }
    } else {
        float* Op = g_Opart + (size_t)ch * BATCH * SEQ * HD;
#pragma unroll
        for (int t = 0; t < 16; t++) {
            int h = 8 * t + 2 * tig;
            *(float2*)&Op[((size_t)b * SEQ + row0) * HD + h]     = make_float2(o[t][0], o[t][1]);
            *(float2*)&Op[((size_t)b * SEQ + row0 + 8) * HD + h] = make_float2(o[t][2], o[t][3]);
        }
        if (tig == 0) {
            g_lpart[ch * BATCH * SEQ + b * SEQ + row0]     = l0;
            g_lpart[ch * BATCH * SEQ + b * SEQ + row0 + 8] = l1;
        }
        __threadfence();
        __syncthreads();
        __shared__ int s_last;
        if (tid == 0) {
            int old = atomicAdd(&g_cnt[b * 16 + qt], 1);
            s_last = (old == nch - 1) ? 1 : 0;
        }
        __syncthreads();
        if (s_last) {
            __threadfence();
#pragma unroll 4
            for (int u = 0; u < 16; u++) {
                int flat = u * 256 + tid;
                int c4 = flat & 31, rl = flat >> 5;
                size_t row = (size_t)b * SEQ + qt * 128 + rl;
                float l = 0.0f;
                float4 o4 = make_float4(0.f, 0.f, 0.f, 0.f);
                for (int c = 0; c < nch; c++) {
                    l += g_lpart[c * BATCH * SEQ + row];
                    float4 v = *(const float4*)&g_Opart[(size_t)c * BATCH * SEQ * HD + row * HD + c4 * 4];
                    o4.x += v.x; o4.y += v.y; o4.z += v.z; o4.w += v.w;
                }
                float inv = 1.0f / l;
                *(float4*)&out[row * HD + c4 * 4] =
                    make_float4(o4.x * inv, o4.y * inv, o4.z * inv, o4.w * inv);
            }
        }
    }
}

// ---------------------------------------------------------------------------
// Fused persistent kernel: work queue over 256 proj items + 576 attn items.
// ---------------------------------------------------------------------------
__global__ __launch_bounds__(256, 1) void fused_kernel(
    const float* __restrict__ x, float* __restrict__ out)
{
    extern __shared__ char smc[];
    __shared__ int s_item;

    for (;;) {
        __syncthreads();
        if (threadIdx.x == 0) s_item = atomicAdd(&g_qhead, 1);
        __syncthreads();
        int it = s_item;
        if (it >= N_ITEMS) return;
        if (it < N_PROJ) do_proj(it, x, smc);
        else             do_attn(it - N_PROJ, out, smc);
    }
}

// ---------------------------------------------------------------------------
extern "C" void kernel_launch(void* const* d_in, const int* in_sizes, int n_in,
                              void* d_out, int out_size)
{
    const float* x  = (const float*)d_in[0];
    const float* Wk = (const float*)d_in[1];
    // d_in[2] = W_query: intentionally unused (reference uses W_key for q too)
    const float* Wv = (const float*)d_in[3];
    float* out = (float*)d_out;

    cudaFuncSetAttribute(fused_kernel, cudaFuncAttributeMaxDynamicSharedMemorySize, FU_SMEM);

    transpose_w<<<dim3(8, 32), dim3(32, 8)>>>(Wk, Wv);
    fused_kernel<<<148, 256, FU_SMEM>>>(x, out);
}

// round 9
// speedup vs baseline: 1.1902x; 1.1902x over previous
#include <cuda_runtime.h>
#include <cuda_fp16.h>
#include <cstdint>

#define BATCH 8
#define SEQ   2048
#define EMB   1024
#define HD    128

// K pre-scale: sqrt(HD^-0.5 * log2(e)) — applied to K (which is also Q), so
// S_raw * HD^-0.5 * log2e comes out of the MMA directly -> P = ex2(S').
#define KSCALE 0.35709512f

// ---------------- scratch (allocation-free rule) ----------------
__device__ __half g_Kh [BATCH * SEQ * HD];       // K(scaled), fp16, h interleaved-16
__device__ __half g_Vth[BATCH * HD * SEQ];       // V^T [b][h][t], fp16, t interleaved-16
__device__ __half g_Wh [2 * HD * EMB];           // [Wk^T;Wv^T] [256][1024], c interleaved-16
__device__ float  g_Opart[8 * BATCH * SEQ * HD]; // per-chunk unnormalized O
__device__ float  g_lpart[8 * BATCH * SEQ];      // per-chunk row sums
__device__ int    g_cnt[BATCH * 32];             // per (b, qt64) finished-chunk counters

// Attn items: (qt, ch), q-tile = 64 rows, chunk = kv64 tiles [4ch, min(4ch+4, qt+1)).
// 120 full-4 chunks (qt desc), then len3, len2, len1 partials. 144 total per batch.
__constant__ unsigned char ITEM_QT[144] = {
    31,31,31,31,31,31,31,31, 30,30,30,30,30,30,30, 29,29,29,29,29,29,29,
    28,28,28,28,28,28,28, 27,27,27,27,27,27,27, 26,26,26,26,26,26,
    25,25,25,25,25,25, 24,24,24,24,24,24, 23,23,23,23,23,23,
    22,22,22,22,22, 21,21,21,21,21, 20,20,20,20,20, 19,19,19,19,19,
    18,18,18,18, 17,17,17,17, 16,16,16,16, 15,15,15,15,
    14,14,14, 13,13,13, 12,12,12, 11,11,11, 10,10, 9,9, 8,8, 7,7,
    6, 5, 4, 3,
    30,26,22,18,14,10,6,2, 29,25,21,17,13,9,5,1, 28,24,20,16,12,8,4,0 };
__constant__ unsigned char ITEM_CH[144] = {
    0,1,2,3,4,5,6,7, 0,1,2,3,4,5,6, 0,1,2,3,4,5,6,
    0,1,2,3,4,5,6, 0,1,2,3,4,5,6, 0,1,2,3,4,5,
    0,1,2,3,4,5, 0,1,2,3,4,5, 0,1,2,3,4,5,
    0,1,2,3,4, 0,1,2,3,4, 0,1,2,3,4, 0,1,2,3,4,
    0,1,2,3, 0,1,2,3, 0,1,2,3, 0,1,2,3,
    0,1,2, 0,1,2, 0,1,2, 0,1,2, 0,1, 0,1, 0,1, 0,1,
    0, 0, 0, 0,
    7,6,5,4,3,2,1,0, 7,6,5,4,3,2,1,0, 7,6,5,4,3,2,1,0 };

// ---------------- helpers ----------------
__device__ __forceinline__ void cp16(void* s, const void* g) {
    asm volatile("cp.async.cg.shared.global [%0], [%1], 16;"
                 :: "r"((uint32_t)__cvta_generic_to_shared(s)), "l"(g));
}
#define CP_COMMIT() asm volatile("cp.async.commit_group;" ::: "memory")
template <int N>
__device__ __forceinline__ void cp_wait() {
    asm volatile("cp.async.wait_group %0;" :: "n"(N) : "memory");
}
__device__ __forceinline__ uint32_t packh2(float lo, float hi) {
    uint32_t d;
    asm("cvt.rn.f16x2.f32 %0, %1, %2;" : "=r"(d) : "f"(hi), "f"(lo));
    return d;
}
__device__ __forceinline__ float ex2(float x) {
    float y; asm("ex2.approx.ftz.f32 %0, %1;" : "=f"(y) : "f"(x)); return y;
}
__device__ __forceinline__ void mma16(float* d, const uint32_t* a, uint32_t b0, uint32_t b1) {
    asm volatile("mma.sync.aligned.m16n8k16.row.col.f32.f16.f16.f32 "
        "{%0,%1,%2,%3}, {%4,%5,%6,%7}, {%8,%9}, {%0,%1,%2,%3};"
        : "+f"(d[0]), "+f"(d[1]), "+f"(d[2]), "+f"(d[3])
        : "r"(a[0]), "r"(a[1]), "r"(a[2]), "r"(a[3]), "r"(b0), "r"(b1));
}
__device__ __forceinline__ int pos16(int c) {   // [0,1,8,9,2,3,10,11,4,5,12,13,6,7,14,15]
    return 4 * ((c & 7) >> 1) + 2 * ((c >> 3) & 1) + (c & 1);
}

// ---------------------------------------------------------------------------
// Kernel 0: W -> g_Wh (half, transposed, c interleaved-16); reset counters.
// ---------------------------------------------------------------------------
__global__ void transpose_w(const float* __restrict__ Wk, const float* __restrict__ Wv) {
    __shared__ float t[32][33];
    if (blockIdx.x == 0 && blockIdx.y == 0) {
        int f = threadIdx.y * 32 + threadIdx.x;
        if (f < BATCH * 32) g_cnt[f] = 0;
    }
    const int n0 = blockIdx.x * 32;
    const int c0 = blockIdx.y * 32;
    const float* W = (blockIdx.x < 4) ? Wk : Wv;
    const int nb = (blockIdx.x & 3) * 32;
    for (int r = threadIdx.y; r < 32; r += 8)
        t[r][threadIdx.x] = W[(size_t)(c0 + r) * HD + nb + threadIdx.x];
    __syncthreads();
    for (int r = threadIdx.y; r < 32; r += 8) {
        int c = c0 + threadIdx.x;
        int cs = (c & ~15) + pos16(c & 15);
        g_Wh[(size_t)(n0 + r) * EMB + cs] = __float2half(t[threadIdx.x][r]);
    }
}

// ---------------------------------------------------------------------------
// Kernel 1: projection. C[128m x 128n] = x_tile @ W(wsel). 256 thr, 2 CTAs/SM.
// kc=64, 2-stage. Swizzled unpadded stages: A [128][256B], B [128][128B].
// ---------------------------------------------------------------------------
#define PJ_AB   32768
#define PJ_ST   (32768 + 16384)     // 49152
#define PJ_SMEM (2 * PJ_ST)         // 98304

__global__ __launch_bounds__(256, 2) void proj_kernel(const float* __restrict__ x) {
    extern __shared__ char smc[];
    const int tid = threadIdx.x, w = tid >> 5, lane = tid & 31;
    const int gid = lane >> 2, tig = lane & 3;
    const int wm = w & 3, wn = w >> 2;
    const int wsel = blockIdx.x;
    const int m0 = blockIdx.y * 128;
    const int swadd = 4 * (gid & 3);

    float acc[16][4];
#pragma unroll
    for (int t = 0; t < 16; t++)
#pragma unroll
        for (int v = 0; v < 4; v++) acc[t][v] = 0.0f;

    auto issue = [&](int st, int c) {
        char* As = smc + st * PJ_ST;
        char* Bs = As + PJ_AB;
#pragma unroll
        for (int q = 0; q < 8; q++) {     // A: 128 rows x 256B, swizzled 16B segs
            int f = q * 256 + tid, r = f >> 4, m = f & 15;
            cp16(As + r * 256 + (((m + 2 * (r & 3)) & 15) << 4),
                 &x[(size_t)(m0 + r) * EMB + c * 64 + m * 4]);
        }
#pragma unroll
        for (int q = 0; q < 4; q++) {     // B: 128 rows x 128B
            int f = q * 256 + tid, r = f >> 3, m = f & 7;
            cp16(Bs + r * 128 + (((m + 2 * (r & 3)) & 7) << 4),
                 &g_Wh[(size_t)(wsel * 128 + r) * EMB + c * 64 + m * 8]);
        }
    };

    issue(0, 0); CP_COMMIT();

    for (int c = 0; c < 16; c++) {
        if (c + 1 < 16) issue((c + 1) & 1, c + 1);
        CP_COMMIT();
        cp_wait<1>();
        __syncthreads();

        const float* As = (const float*)(smc + (c & 1) * PJ_ST);
        const __half* Bs = (const __half*)(smc + (c & 1) * PJ_ST + PJ_AB);
#pragma unroll
        for (int ks = 0; ks < 4; ks++) {
            uint32_t a[2][4];
            const int ulo = (8 * ks + tig + swadd) & 31;
            const int uhi = (8 * ks + tig + 4 + swadd) & 31;
#pragma unroll
            for (int mi = 0; mi < 2; mi++) {
                int r = 32 * wm + 16 * mi + gid;
                float2 lo0 = *(const float2*)(As + r * 64 + ulo * 2);
                float2 lo1 = *(const float2*)(As + (r + 8) * 64 + ulo * 2);
                float2 hi0 = *(const float2*)(As + r * 64 + uhi * 2);
                float2 hi1 = *(const float2*)(As + (r + 8) * 64 + uhi * 2);
                a[mi][0] = packh2(lo0.x, lo0.y);
                a[mi][1] = packh2(lo1.x, lo1.y);
                a[mi][2] = packh2(hi0.x, hi0.y);
                a[mi][3] = packh2(hi1.x, hi1.y);
            }
            const int ub = (4 * ks + tig + swadd) & 15;
#pragma unroll
            for (int ni = 0; ni < 8; ni++) {
                int rB = 64 * wn + 8 * ni + gid;
                uint2 bb = *(const uint2*)(Bs + rB * 64 + ub * 4);
                mma16(acc[ni],     a[0], bb.x, bb.y);
                mma16(acc[8 + ni], a[1], bb.x, bb.y);
            }
        }
        __syncthreads();
    }

    if (wsel == 0) {
        // g_Kh scaled by KSCALE, h interleaved-16
#pragma unroll
        for (int mi = 0; mi < 2; mi++) {
            int r0 = m0 + 32 * wm + 16 * mi + gid;
#pragma unroll
            for (int ni = 0; ni < 8; ni++) {
                int n = 64 * wn + 8 * ni + 2 * tig;
                int hst = (n & ~15) + pos16(n & 15);
                float* ac = acc[mi * 8 + ni];
                *(__half2*)&g_Kh[(size_t)r0 * HD + hst] =
                    __floats2half2_rn(ac[0] * KSCALE, ac[1] * KSCALE);
                *(__half2*)&g_Kh[(size_t)(r0 + 8) * HD + hst] =
                    __floats2half2_rn(ac[2] * KSCALE, ac[3] * KSCALE);
            }
        }
    } else {
        // V^T via smem staging [h=128][t=128 pad 136], then coalesced 16B stores
        __half* vs = (__half*)smc;
#pragma unroll
        for (int mi = 0; mi < 2; mi++) {
            int tl = 32 * wm + 16 * mi + gid;
            int ts0 = (tl & ~15) + pos16(gid);
            int ts1 = ts0 + 2;                   // pos16(gid+8) = pos16(gid)+2
#pragma unroll
            for (int ni = 0; ni < 8; ni++) {
                int h0 = 64 * wn + 8 * ni + 2 * tig;
                float* ac = acc[mi * 8 + ni];
                vs[h0 * 136 + ts0]       = __float2half(ac[0]);
                vs[(h0 + 1) * 136 + ts0] = __float2half(ac[1]);
                vs[h0 * 136 + ts1]       = __float2half(ac[2]);
                vs[(h0 + 1) * 136 + ts1] = __float2half(ac[3]);
            }
        }
        __syncthreads();
        const int bb = m0 >> 11;
        const int tb = m0 & 2047;
        __half* dst = g_Vth + (size_t)bb * HD * SEQ;
#pragma unroll
        for (int q = 0; q < 8; q++) {
            int f = q * 256 + tid, r = f >> 4, m = f & 15;
            uint4 v = *(uint4*)&vs[r * 136 + m * 8];
            *(uint4*)&dst[(size_t)r * SEQ + tb + m * 8] = v;
        }
    }
}

// ---------------------------------------------------------------------------
// Kernel 2: attention + fused combine. 128 threads, 64 q-rows, kv64 tiles,
// 3 CTAs/SM. smem (halves): K0@0 K1@8192 V0@16384 V1@24576. 64KB total.
// ---------------------------------------------------------------------------
#define AT_SMEM 65536

__global__ __launch_bounds__(128, 3) void attn_kernel(float* __restrict__ out) {
    extern __shared__ __half smh[];
    const int tid = threadIdx.x, w = tid >> 5, lane = tid & 31;
    const int gid = lane >> 2, tig = lane & 3;
    const int b = blockIdx.x;
    const int qt = ITEM_QT[blockIdx.y];
    const int ch = ITEM_CH[blockIdx.y];
    const int jbeg = 4 * ch;
    const int jend = min(4 * ch + 4, qt + 1);
    const int nch = (qt + 4) >> 2;
    const int swadd = 4 * (gid & 3);

    const __half* Kbh  = g_Kh  + (size_t)b * SEQ * HD;
    const __half* Vtbh = g_Vth + (size_t)b * HD * SEQ;

    auto stage = [&](int jj, int bsel) {
        const int tok0 = jj * 64;
        __half* Ks = smh + bsel * 8192;
        __half* Vs = smh + 16384 + bsel * 8192;
#pragma unroll
        for (int q = 0; q < 8; q++) {          // K: 64 rows x 256B
            int f = q * 128 + tid, r = f >> 4, m = f & 15;
            cp16(Ks + r * 128 + (((m + 2 * (r & 3)) & 15) << 3),
                 &Kbh[(size_t)(tok0 + r) * HD + m * 8]);
        }
#pragma unroll
        for (int q = 0; q < 8; q++) {          // V: 128 rows x 128B
            int f = q * 128 + tid, r = f >> 3, m = f & 7;
            cp16(Vs + r * 64 + (((m + 2 * (r & 3)) & 7) << 3),
                 &Vtbh[(size_t)r * SEQ + tok0 + m * 8]);
        }
    };

    stage(jbeg, 0); CP_COMMIT();

    // Q fragments from gmem (q = key(x) source bug: read g_Kh)
    const int qrow = qt * 64 + 16 * w + gid;
    const uint2* Qg0 = (const uint2*)(Kbh + (size_t)qrow * HD);
    const uint2* Qg8 = (const uint2*)(Kbh + (size_t)(qrow + 8) * HD);
    uint32_t qa[8][4];
#pragma unroll
    for (int ks = 0; ks < 8; ks++) {
        uint2 u0 = Qg0[4 * ks + tig];
        uint2 u1 = Qg8[4 * ks + tig];
        qa[ks][0] = u0.x; qa[ks][2] = u0.y;
        qa[ks][1] = u1.x; qa[ks][3] = u1.y;
    }

    float o[16][4];
#pragma unroll
    for (int t = 0; t < 16; t++)
#pragma unroll
        for (int v = 0; v < 4; v++) o[t][v] = 0.0f;
    float l0 = 0.0f, l1 = 0.0f;

    const int qr0 = qt * 64 + 16 * w;

    for (int jj = jbeg; jj < jend; jj++) {
        const int buf = (jj - jbeg) & 1;
        if (jj + 1 < jend) stage(jj + 1, buf ^ 1);
        CP_COMMIT();
        cp_wait<1>();
        __syncthreads();

        const __half* Ks = smh + buf * 8192;
        const __half* Vs = smh + 16384 + buf * 8192;

        // ---- S' = (scaled Q)(scaled K)^T : 16q x 64kv per warp ----
        float s[8][4];
#pragma unroll
        for (int t = 0; t < 8; t++)
#pragma unroll
            for (int v = 0; v < 4; v++) s[t][v] = 0.0f;

#pragma unroll
        for (int ks = 0; ks < 8; ks++) {
            const int u = (4 * ks + tig + swadd) & 31;
#pragma unroll
            for (int t = 0; t < 8; t++) {
                uint2 bb = *(const uint2*)(Ks + (8 * t + gid) * 128 + u * 4);
                mma16(s[t], qa[ks], bb.x, bb.y);
            }
        }

        // ---- P = ex2(S'), causal mask (diag tile only), row sums ----
        const int kv0 = jj * 64;
        const bool domask = (jj == qt);
#pragma unroll
        for (int t = 0; t < 8; t++) {
            const int col = kv0 + 8 * t + 2 * tig;
            float p0 = ex2(s[t][0]);
            float p1 = ex2(s[t][1]);
            float p2 = ex2(s[t][2]);
            float p3 = ex2(s[t][3]);
            if (domask) {
                const int r0 = qr0 + gid, r1 = r0 + 8;
                if (col > r0)     p0 = 0.0f;
                if (col + 1 > r0) p1 = 0.0f;
                if (col > r1)     p2 = 0.0f;
                if (col + 1 > r1) p3 = 0.0f;
            }
            l0 += p0 + p1;
            l1 += p2 + p3;
            s[t][0] = p0; s[t][1] = p1; s[t][2] = p2; s[t][3] = p3;
        }

        // ---- O += P V (C-as-A packing) ----
#pragma unroll
        for (int ks = 0; ks < 4; ks++) {
            uint32_t a[4];
            a[0] = packh2(s[2 * ks][0],     s[2 * ks][1]);
            a[1] = packh2(s[2 * ks][2],     s[2 * ks][3]);
            a[2] = packh2(s[2 * ks + 1][0], s[2 * ks + 1][1]);
            a[3] = packh2(s[2 * ks + 1][2], s[2 * ks + 1][3]);
            const int u = (4 * ks + tig + swadd) & 15;
#pragma unroll
            for (int t = 0; t < 16; t++) {
                uint2 bb = *(const uint2*)(Vs + (8 * t + gid) * 64 + u * 4);
                mma16(o[t], a, bb.x, bb.y);
            }
        }
        __syncthreads();
    }

    // quad-reduce row sums
#pragma unroll
    for (int off = 1; off < 4; off <<= 1) {
        l0 += __shfl_xor_sync(0xffffffffu, l0, off);
        l1 += __shfl_xor_sync(0xffffffffu, l1, off);
    }

    const int row0 = qt * 64 + 16 * w + gid;
    if (nch == 1) {
        const float i0 = 1.0f / l0, i1 = 1.0f / l1;
#pragma unroll
        for (int t = 0; t < 16; t++) {
            int h = 8 * t + 2 * tig;
            *(float2*)&out[((size_t)b * SEQ + row0) * HD + h] =
                make_float2(o[t][0] * i0, o[t][1] * i0);
            *(float2*)&out[((size_t)b * SEQ + row0 + 8) * HD + h] =
                make_float2(o[t][2] * i1, o[t][3] * i1);
        }
    } else {
        float* Op = g_Opart + (size_t)ch * BATCH * SEQ * HD;
#pragma unroll
        for (int t = 0; t < 16; t++) {
            int h = 8 * t + 2 * tig;
            *(float2*)&Op[((size_t)b * SEQ + row0) * HD + h]     = make_float2(o[t][0], o[t][1]);
            *(float2*)&Op[((size_t)b * SEQ + row0 + 8) * HD + h] = make_float2(o[t][2], o[t][3]);
        }
        if (tig == 0) {
            g_lpart[ch * BATCH * SEQ + b * SEQ + row0]     = l0;
            g_lpart[ch * BATCH * SEQ + b * SEQ + row0 + 8] = l1;
        }
        __threadfence();
        __syncthreads();
        __shared__ int s_last;
        if (tid == 0) {
            int old = atomicAdd(&g_cnt[b * 32 + qt], 1);
            s_last = (old == nch - 1) ? 1 : 0;
        }
        __syncthreads();
        if (s_last) {
            __threadfence();
#pragma unroll 4
            for (int u = 0; u < 16; u++) {
                int flat = u * 128 + tid;
                int c4 = flat & 31, rl = flat >> 5;
                size_t row = (size_t)b * SEQ + qt * 64 + rl;
                float l = 0.0f;
                float4 o4 = make_float4(0.f, 0.f, 0.f, 0.f);
                for (int c = 0; c < nch; c++) {
                    l += g_lpart[c * BATCH * SEQ + row];
                    float4 v = *(const float4*)&g_Opart[(size_t)c * BATCH * SEQ * HD + row * HD + c4 * 4];
                    o4.x += v.x; o4.y += v.y; o4.z += v.z; o4.w += v.w;
                }
                float inv = 1.0f / l;
                *(float4*)&out[row * HD + c4 * 4] =
                    make_float4(o4.x * inv, o4.y * inv, o4.z * inv, o4.w * inv);
            }
        }
    }
}

// ---------------------------------------------------------------------------
extern "C" void kernel_launch(void* const* d_in, const int* in_sizes, int n_in,
                              void* d_out, int out_size)
{
    const float* x  = (const float*)d_in[0];
    const float* Wk = (const float*)d_in[1];
    // d_in[2] = W_query: intentionally unused (reference uses W_key for q too)
    const float* Wv = (const float*)d_in[3];
    float* out = (float*)d_out;

    cudaFuncSetAttribute(proj_kernel, cudaFuncAttributeMaxDynamicSharedMemorySize, PJ_SMEM);
    cudaFuncSetAttribute(attn_kernel, cudaFuncAttributeMaxDynamicSharedMemorySize, AT_SMEM);

    transpose_w<<<dim3(8, 32), dim3(32, 8)>>>(Wk, Wv);
    proj_kernel<<<dim3(2, 128), 256, PJ_SMEM>>>(x);     // x=wsel fast: K/V pair shares x in L2
    attn_kernel<<<dim3(8, 144), 128, AT_SMEM>>>(out);   // x=batch fast: big items first
}